// round 16
// baseline (speedup 1.0000x reference)
#include <cuda_runtime.h>
#include <cuda_fp16.h>

#define N_NODES 50000
#define IN_CH   128
#define F1      128     // HEADS*HID
#define HEADS   4
#define HID     32
#define OUT_CH  8
#define NEG_SLOPE 0.2f
#define CAP     96      // per-dst bucket capacity (max degree ~45 for Poisson(16))
#define ESCALE  0.015625f   // 1/64: fp16 overflow/subnormal guard for HFMA2 path

// ---------------- scratch (device globals; zero-initialized at load) ---------
__device__ __half g_h1h[N_NODES * F1];     // layer-1 linear output (fp16)
__device__ float g_as1[N_NODES * HEADS];
__device__ float g_ad1[N_NODES * HEADS];
__device__ float g_h2 [N_NODES * OUT_CH];
__device__ float g_as2[N_NODES];
__device__ float g_ad2[N_NODES];
// padded-bucket adjacency (by destination)
__device__ int g_cnt[N_NODES];             // invariant: zero at entry AND exit
__device__ int g_srclist[N_NODES * CAP];

__device__ __forceinline__ float lrelu(float x) { return x > 0.f ? x : NEG_SLOPE * x; }

// ---------------- C1: scatter real edges into padded buckets (2/thread) ------
__global__ void k_scatter(const int* __restrict__ ei, int E) {
    int e2 = (blockIdx.x * blockDim.x + threadIdx.x) * 2;
    if (e2 + 1 < E) {
        int2 s = *reinterpret_cast<const int2*>(&ei[e2]);
        int2 d = *reinterpret_cast<const int2*>(&ei[E + e2]);
        int p0 = atomicAdd(&g_cnt[d.x], 1);
        int p1 = atomicAdd(&g_cnt[d.y], 1);
        p0 = p0 < CAP ? p0 : CAP - 1;      // clamp (never hit in practice)
        p1 = p1 < CAP ? p1 : CAP - 1;
        g_srclist[d.x * CAP + p0] = s.x;
        g_srclist[d.y * CAP + p1] = s.y;
    } else if (e2 < E) {
        int d = ei[E + e2];
        int pos = atomicAdd(&g_cnt[d], 1);
        pos = pos < CAP ? pos : CAP - 1;
        g_srclist[d * CAP + pos] = ei[e2];
    }
}

// ---------------- K1: h1 = x @ W1 ; alpha_src1/alpha_dst1 (R6 form) ----------
// 128 threads, 16 rows/block; packed f32x2 FMA; conflict-free epilogue
__global__ void __launch_bounds__(128) k_gemm1(
        const float* __restrict__ x, const float* __restrict__ W1,
        const float* __restrict__ a_src1, const float* __restrict__ a_dst1,
        int N) {
    __shared__ float xs2[IN_CH][20];   // [k][r]; 20-float rows (16B aligned)
    __shared__ float hs[16][F1];
    const int t = threadIdx.x;            // output column 0..127
    const int row0 = blockIdx.x * 16;

    #pragma unroll
    for (int r = 0; r < 16; r++) {
        int n = row0 + r;
        xs2[t][r] = (n < N) ? x[n * IN_CH + t] : 0.f;
    }
    __syncthreads();

    unsigned long long accp[8];            // accp[p] = rows (2p, 2p+1)
    #pragma unroll
    for (int i = 0; i < 8; i++) accp[i] = 0ull;

    #pragma unroll 4
    for (int k = 0; k < IN_CH; k++) {
        float w = W1[k * F1 + t];
        unsigned long long w2;
        asm("mov.b64 %0, {%1, %1};" : "=l"(w2) : "f"(w));
        const ulonglong2* xr = reinterpret_cast<const ulonglong2*>(&xs2[k][0]);
        #pragma unroll
        for (int i = 0; i < 4; i++) {
            ulonglong2 u = xr[i];          // rows 4i..4i+3 (broadcast load)
            asm("fma.rn.f32x2 %0, %1, %2, %0;" : "+l"(accp[2*i  ]) : "l"(u.x), "l"(w2));
            asm("fma.rn.f32x2 %0, %1, %2, %0;" : "+l"(accp[2*i+1]) : "l"(u.y), "l"(w2));
        }
    }

    #pragma unroll
    for (int i = 0; i < 8; i++) {
        float lo, hi;
        asm("mov.b64 {%0, %1}, %2;" : "=f"(lo), "=f"(hi) : "l"(accp[i]));
        int r0 = 2 * i, r1 = 2 * i + 1;
        hs[r0][t] = lo;
        hs[r1][t] = hi;
        int n0 = row0 + r0, n1 = row0 + r1;
        if (n0 < N) g_h1h[n0 * F1 + t] = __float2half(lo);
        if (n1 < N) g_h1h[n1 * F1 + t] = __float2half(hi);
    }
    __syncthreads();

    // 16 rows * 4 heads * {src,dst} = 128 tasks, one per thread (rotated index)
    const int r    = t >> 3;
    const int q    = t & 7;
    const int head = q & 3;
    const bool is_dst = (q >= 4);
    const float* a = is_dst ? a_dst1 : a_src1;
    float s = 0.f;
    #pragma unroll
    for (int c0 = 0; c0 < HID; c0++) {
        int c = (c0 + t) & (HID - 1);
        s += hs[r][head * HID + c] * a[head * HID + c];
    }
    int n = row0 + r;
    if (n < N) {
        if (is_dst) g_ad1[n * HEADS + head] = s;
        else        g_as1[n * HEADS + head] = s;
    }
}

// ---------------- K2: fused layer-1 agg + ELU + layer-2 linear ---------------
// warp per dst node; HFMA2 inner accumulation (no F2F in the hot loop),
// fp32 flush every 8 edges; edge weights pre-scaled by 1/64 (fp16 range guard)
__global__ void __launch_bounds__(256) k_agg1(
        const float* __restrict__ b1, const float* __restrict__ W2,
        const float* __restrict__ a_src2, const float* __restrict__ a_dst2,
        int N) {
    __shared__ float W2t[OUT_CH][F1];      // transposed: W2t[o][c] = W2[c*8+o]
    __shared__ float a2s[OUT_CH], a2d[OUT_CH];
    {
        int tt = threadIdx.x;
        for (int i = tt; i < F1 * OUT_CH; i += blockDim.x) {
            int c = i >> 3, o = i & 7;
            W2t[o][c] = W2[i];
        }
        if (tt < OUT_CH) { a2s[tt] = a_src2[tt]; a2d[tt] = a_dst2[tt]; }
        __syncthreads();
    }

    int w    = (blockIdx.x * blockDim.x + threadIdx.x) >> 5;   // dst node
    int lane = threadIdx.x & 31;
    if (w >= N) return;
    const int head = lane >> 3;
    const float ad = g_ad1[w * HEADS + head];
    const int cnt  = g_cnt[w];
    const int base = w * CAP;

    const uint2* h1v = reinterpret_cast<const uint2*>(g_h1h);

    // self-loop (s = w) in fp32, scaled by ESCALE like everything else
    float4 acc;   // scaled fp32 accumulator
    float den;    // UNscaled denominator
    {
        float e = __expf(lrelu(g_as1[w * HEADS + head] + ad));
        float es = e * ESCALE;
        uint2 u = h1v[w * 32 + lane];
        float2 f0 = __half22float2(*reinterpret_cast<const __half2*>(&u.x));
        float2 f1 = __half22float2(*reinterpret_cast<const __half2*>(&u.y));
        den   = e;
        acc.x = es * f0.x;
        acc.y = es * f0.y;
        acc.z = es * f1.x;
        acc.w = es * f1.y;
    }

    __half2 ah0 = __floats2half2_rn(0.f, 0.f);
    __half2 ah1 = __floats2half2_rn(0.f, 0.f);
    #pragma unroll 4
    for (int j = 0; j < cnt; j++) {
        int s = g_srclist[base + j];
        float e = __expf(lrelu(g_as1[s * HEADS + head] + ad));
        den += e;
        __half2 eh = __float2half2_rn(e * ESCALE);
        uint2 u = h1v[s * 32 + lane];                 // 4 halves
        ah0 = __hfma2(eh, *reinterpret_cast<const __half2*>(&u.x), ah0);
        ah1 = __hfma2(eh, *reinterpret_cast<const __half2*>(&u.y), ah1);
        if ((j & 7) == 7) {                           // fp32 flush every 8 edges
            float2 p0 = __half22float2(ah0);
            float2 p1 = __half22float2(ah1);
            acc.x += p0.x; acc.y += p0.y;
            acc.z += p1.x; acc.w += p1.y;
            ah0 = __floats2half2_rn(0.f, 0.f);
            ah1 = __floats2half2_rn(0.f, 0.f);
        }
    }
    {   // final flush
        float2 p0 = __half22float2(ah0);
        float2 p1 = __half22float2(ah1);
        acc.x += p0.x; acc.y += p0.y;
        acc.z += p1.x; acc.w += p1.y;
    }

    float inv = __frcp_rn(den) * 64.0f;   // undo ESCALE
    float4 bias = reinterpret_cast<const float4*>(b1)[lane];
    float v0 = acc.x * inv + bias.x;
    float v1 = acc.y * inv + bias.y;
    float v2 = acc.z * inv + bias.z;
    float v3 = acc.w * inv + bias.w;
    // ELU via fast exp
    v0 = v0 > 0.f ? v0 : (__expf(v0) - 1.f);
    v1 = v1 > 0.f ? v1 : (__expf(v1) - 1.f);
    v2 = v2 > 0.f ? v2 : (__expf(v2) - 1.f);
    v3 = v3 > 0.f ? v3 : (__expf(v3) - 1.f);

    // h2 = elu(out1) @ W2  — conflict-free: lanes read W2t[o][lane*4..+3]
    float h2v[OUT_CH];
    #pragma unroll
    for (int o = 0; o < OUT_CH; o++) {
        float4 wv = *reinterpret_cast<const float4*>(&W2t[o][lane * 4]);
        float p = v0 * wv.x + v1 * wv.y + v2 * wv.z + v3 * wv.w;
        #pragma unroll
        for (int off = 16; off; off >>= 1) p += __shfl_xor_sync(0xFFFFFFFFu, p, off);
        h2v[o] = p;
    }
    if (lane < OUT_CH) g_h2[w * OUT_CH + lane] = h2v[lane];
    if (lane == 0) {
        float s1 = 0.f, s2 = 0.f;
        #pragma unroll
        for (int o = 0; o < OUT_CH; o++) { s1 += h2v[o] * a2s[o]; s2 += h2v[o] * a2d[o]; }
        g_as2[w] = s1;
        g_ad2[w] = s2;
    }
}

// ---------------- K3: fused layer-2 softmax + aggregation --------------------
// warp per dst node: 4 edge-slots x 8 channels; self-loop inline; resets g_cnt
__global__ void __launch_bounds__(256) k_agg2(
        const float* __restrict__ b2, float* __restrict__ out, int N) {
    int w    = (blockIdx.x * blockDim.x + threadIdx.x) >> 5;   // dst node
    int lane = threadIdx.x & 31;
    if (w >= N) return;
    const int eg   = lane >> 3;   // edge slot 0..3
    const int chan = lane & 7;
    const float ad = g_ad2[w];
    const int cnt  = g_cnt[w];
    const int base = w * CAP;
    float acc = 0.f, den = 0.f;
    // self-loop on slot 0
    if (eg == 0) {
        float e = __expf(lrelu(g_as2[w] + ad));
        den += e;
        acc += e * g_h2[w * OUT_CH + chan];
    }
    for (int j = eg; j < cnt; j += 4) {
        int s = g_srclist[base + j];
        float e = __expf(lrelu(g_as2[s] + ad));
        den += e;
        acc += e * g_h2[s * OUT_CH + chan];
    }
    // reduce across the 4 edge slots
    acc += __shfl_xor_sync(0xFFFFFFFFu, acc, 8);
    acc += __shfl_xor_sync(0xFFFFFFFFu, acc, 16);
    den += __shfl_xor_sync(0xFFFFFFFFu, den, 8);
    den += __shfl_xor_sync(0xFFFFFFFFu, den, 16);
    if (lane < OUT_CH) out[w * OUT_CH + lane] = acc / den + b2[lane];
    __syncwarp();
    if (lane == 0) g_cnt[w] = 0;   // restore invariant for next replay
}

// ---------------- launcher ---------------------------------------------------
extern "C" void kernel_launch(void* const* d_in, const int* in_sizes, int n_in,
                              void* d_out, int out_size) {
    const float* x      = (const float*)d_in[0];
    const int*   ei     = (const int*)  d_in[1];   // int32 (JAX x64 disabled)
    const float* W1     = (const float*)d_in[2];
    const float* a_src1 = (const float*)d_in[3];
    const float* a_dst1 = (const float*)d_in[4];
    const float* b1     = (const float*)d_in[5];
    const float* W2     = (const float*)d_in[6];
    const float* a_src2 = (const float*)d_in[7];
    const float* a_dst2 = (const float*)d_in[8];
    const float* b2     = (const float*)d_in[9];
    float*       out    = (float*)      d_out;

    const int N = in_sizes[0] / IN_CH;   // 50000
    const int E = in_sizes[1] / 2;       // 800000

    // side stream + events, created once on the (uncaptured) correctness call
    static cudaStream_t s2 = []() {
        cudaStream_t s; cudaStreamCreateWithFlags(&s, cudaStreamNonBlocking); return s;
    }();
    static cudaEvent_t ev0 = []() {
        cudaEvent_t e; cudaEventCreateWithFlags(&e, cudaEventDisableTiming); return e;
    }();
    static cudaEvent_t ev1 = []() {
        cudaEvent_t e; cudaEventCreateWithFlags(&e, cudaEventDisableTiming); return e;
    }();

    // fork: scatter on s2, gemm1 on main stream
    cudaEventRecord(ev0, 0);
    cudaStreamWaitEvent(s2, ev0, 0);

    // --- branch A (s2): padded-bucket scatter (g_cnt zero by invariant) ---
    {
        int nt = (E + 1) / 2;
        k_scatter<<<(nt + 255) / 256, 256, 0, s2>>>(ei, E);
    }
    cudaEventRecord(ev1, s2);

    // --- branch B (main): layer-1 linear ---
    k_gemm1<<<(N + 15) / 16, 128>>>(x, W1, a_src1, a_dst1, N);

    // join
    cudaStreamWaitEvent(0, ev1, 0);

    // fused layer-1 aggregation + ELU + layer-2 linear
    k_agg1<<<(N * 32 + 255) / 256, 256>>>(b1, W2, a_src2, a_dst2, N);
    // layer-2 aggregation (also restores g_cnt = 0)
    k_agg2<<<(N * 32 + 255) / 256, 256>>>(b2, out, N);
}

// round 17
// speedup vs baseline: 1.0283x; 1.0283x over previous
#include <cuda_runtime.h>
#include <cuda_fp16.h>

#define N_NODES 50000
#define IN_CH   128
#define F1      128     // HEADS*HID
#define HEADS   4
#define HID     32
#define OUT_CH  8
#define NEG_SLOPE 0.2f
#define CAP     96      // per-dst bucket capacity (max degree ~45 for Poisson(16))

// ---------------- scratch (device globals; zero-initialized at load) ---------
__device__ __half g_h1h[N_NODES * F1];     // layer-1 linear output (fp16)
__device__ float g_as1[N_NODES * HEADS];
__device__ float g_ad1[N_NODES * HEADS];
__device__ float g_h2 [N_NODES * OUT_CH];
__device__ float g_as2[N_NODES];
__device__ float g_ad2[N_NODES];
// padded-bucket adjacency (by destination)
__device__ int g_cnt[N_NODES];             // invariant: zero at entry AND exit
__device__ int g_srclist[N_NODES * CAP];

__device__ __forceinline__ float lrelu(float x) { return x > 0.f ? x : NEG_SLOPE * x; }

// ---------------- probe: no-op, shifts ncu window onto k_agg1 ----------------
__global__ void k_probe() {}

// ---------------- C1: scatter real edges into padded buckets (2/thread) ------
__global__ void k_scatter(const int* __restrict__ ei, int E) {
    int e2 = (blockIdx.x * blockDim.x + threadIdx.x) * 2;
    if (e2 + 1 < E) {
        int2 s = *reinterpret_cast<const int2*>(&ei[e2]);
        int2 d = *reinterpret_cast<const int2*>(&ei[E + e2]);
        int p0 = atomicAdd(&g_cnt[d.x], 1);
        int p1 = atomicAdd(&g_cnt[d.y], 1);
        p0 = p0 < CAP ? p0 : CAP - 1;      // clamp (never hit in practice)
        p1 = p1 < CAP ? p1 : CAP - 1;
        g_srclist[d.x * CAP + p0] = s.x;
        g_srclist[d.y * CAP + p1] = s.y;
    } else if (e2 < E) {
        int d = ei[E + e2];
        int pos = atomicAdd(&g_cnt[d], 1);
        pos = pos < CAP ? pos : CAP - 1;
        g_srclist[d * CAP + pos] = ei[e2];
    }
}

// ---------------- K1: h1 = x @ W1 ; alpha_src1/alpha_dst1 (R6 form) ----------
// 128 threads, 16 rows/block; packed f32x2 FMA; conflict-free epilogue
__global__ void __launch_bounds__(128) k_gemm1(
        const float* __restrict__ x, const float* __restrict__ W1,
        const float* __restrict__ a_src1, const float* __restrict__ a_dst1,
        int N) {
    __shared__ float xs2[IN_CH][20];   // [k][r]; 20-float rows (16B aligned)
    __shared__ float hs[16][F1];
    const int t = threadIdx.x;            // output column 0..127
    const int row0 = blockIdx.x * 16;

    #pragma unroll
    for (int r = 0; r < 16; r++) {
        int n = row0 + r;
        xs2[t][r] = (n < N) ? x[n * IN_CH + t] : 0.f;
    }
    __syncthreads();

    unsigned long long accp[8];            // accp[p] = rows (2p, 2p+1)
    #pragma unroll
    for (int i = 0; i < 8; i++) accp[i] = 0ull;

    #pragma unroll 4
    for (int k = 0; k < IN_CH; k++) {
        float w = W1[k * F1 + t];
        unsigned long long w2;
        asm("mov.b64 %0, {%1, %1};" : "=l"(w2) : "f"(w));
        const ulonglong2* xr = reinterpret_cast<const ulonglong2*>(&xs2[k][0]);
        #pragma unroll
        for (int i = 0; i < 4; i++) {
            ulonglong2 u = xr[i];          // rows 4i..4i+3 (broadcast load)
            asm("fma.rn.f32x2 %0, %1, %2, %0;" : "+l"(accp[2*i  ]) : "l"(u.x), "l"(w2));
            asm("fma.rn.f32x2 %0, %1, %2, %0;" : "+l"(accp[2*i+1]) : "l"(u.y), "l"(w2));
        }
    }

    #pragma unroll
    for (int i = 0; i < 8; i++) {
        float lo, hi;
        asm("mov.b64 {%0, %1}, %2;" : "=f"(lo), "=f"(hi) : "l"(accp[i]));
        int r0 = 2 * i, r1 = 2 * i + 1;
        hs[r0][t] = lo;
        hs[r1][t] = hi;
        int n0 = row0 + r0, n1 = row0 + r1;
        if (n0 < N) g_h1h[n0 * F1 + t] = __float2half(lo);
        if (n1 < N) g_h1h[n1 * F1 + t] = __float2half(hi);
    }
    __syncthreads();

    // 16 rows * 4 heads * {src,dst} = 128 tasks, one per thread (rotated index)
    const int r    = t >> 3;
    const int q    = t & 7;
    const int head = q & 3;
    const bool is_dst = (q >= 4);
    const float* a = is_dst ? a_dst1 : a_src1;
    float s = 0.f;
    #pragma unroll
    for (int c0 = 0; c0 < HID; c0++) {
        int c = (c0 + t) & (HID - 1);
        s += hs[r][head * HID + c] * a[head * HID + c];
    }
    int n = row0 + r;
    if (n < N) {
        if (is_dst) g_ad1[n * HEADS + head] = s;
        else        g_as1[n * HEADS + head] = s;
    }
}

// ---------------- K2: fused layer-1 agg + ELU + layer-2 linear (R14 form) ----
// warp per dst node; self-loop handled inline; fast-exp ELU
__global__ void __launch_bounds__(256) k_agg1(
        const float* __restrict__ b1, const float* __restrict__ W2,
        const float* __restrict__ a_src2, const float* __restrict__ a_dst2,
        int N) {
    __shared__ float W2t[OUT_CH][F1];      // transposed: W2t[o][c] = W2[c*8+o]
    __shared__ float a2s[OUT_CH], a2d[OUT_CH];
    {
        int tt = threadIdx.x;
        for (int i = tt; i < F1 * OUT_CH; i += blockDim.x) {
            int c = i >> 3, o = i & 7;
            W2t[o][c] = W2[i];
        }
        if (tt < OUT_CH) { a2s[tt] = a_src2[tt]; a2d[tt] = a_dst2[tt]; }
        __syncthreads();
    }

    int w    = (blockIdx.x * blockDim.x + threadIdx.x) >> 5;   // dst node
    int lane = threadIdx.x & 31;
    if (w >= N) return;
    const int head = lane >> 3;
    const float ad = g_ad1[w * HEADS + head];
    const int cnt  = g_cnt[w];
    const int base = w * CAP;

    const uint2* h1v = reinterpret_cast<const uint2*>(g_h1h);

    // self-loop first (s = w)
    float4 acc;
    float den;
    {
        float e = __expf(lrelu(g_as1[w * HEADS + head] + ad));
        uint2 u = h1v[w * 32 + lane];
        float2 f0 = __half22float2(*reinterpret_cast<const __half2*>(&u.x));
        float2 f1 = __half22float2(*reinterpret_cast<const __half2*>(&u.y));
        den   = e;
        acc.x = e * f0.x;
        acc.y = e * f0.y;
        acc.z = e * f1.x;
        acc.w = e * f1.y;
    }
    #pragma unroll 8
    for (int j = 0; j < cnt; j++) {
        int s = g_srclist[base + j];
        float e = __expf(lrelu(g_as1[s * HEADS + head] + ad));
        uint2 u = h1v[s * 32 + lane];                 // 4 halves
        float2 f0 = __half22float2(*reinterpret_cast<const __half2*>(&u.x));
        float2 f1 = __half22float2(*reinterpret_cast<const __half2*>(&u.y));
        den   += e;
        acc.x += e * f0.x;
        acc.y += e * f0.y;
        acc.z += e * f1.x;
        acc.w += e * f1.y;
    }
    float inv = __frcp_rn(den);
    float4 bias = reinterpret_cast<const float4*>(b1)[lane];
    float v0 = acc.x * inv + bias.x;
    float v1 = acc.y * inv + bias.y;
    float v2 = acc.z * inv + bias.z;
    float v3 = acc.w * inv + bias.w;
    // ELU via fast exp
    v0 = v0 > 0.f ? v0 : (__expf(v0) - 1.f);
    v1 = v1 > 0.f ? v1 : (__expf(v1) - 1.f);
    v2 = v2 > 0.f ? v2 : (__expf(v2) - 1.f);
    v3 = v3 > 0.f ? v3 : (__expf(v3) - 1.f);

    // h2 = elu(out1) @ W2  — conflict-free: lanes read W2t[o][lane*4..+3]
    float h2v[OUT_CH];
    #pragma unroll
    for (int o = 0; o < OUT_CH; o++) {
        float4 wv = *reinterpret_cast<const float4*>(&W2t[o][lane * 4]);
        float p = v0 * wv.x + v1 * wv.y + v2 * wv.z + v3 * wv.w;
        #pragma unroll
        for (int off = 16; off; off >>= 1) p += __shfl_xor_sync(0xFFFFFFFFu, p, off);
        h2v[o] = p;
    }
    if (lane < OUT_CH) g_h2[w * OUT_CH + lane] = h2v[lane];
    if (lane == 0) {
        float s1 = 0.f, s2 = 0.f;
        #pragma unroll
        for (int o = 0; o < OUT_CH; o++) { s1 += h2v[o] * a2s[o]; s2 += h2v[o] * a2d[o]; }
        g_as2[w] = s1;
        g_ad2[w] = s2;
    }
}

// ---------------- K3: fused layer-2 softmax + aggregation --------------------
// warp per dst node: 4 edge-slots x 8 channels; self-loop inline; resets g_cnt
__global__ void __launch_bounds__(256) k_agg2(
        const float* __restrict__ b2, float* __restrict__ out, int N) {
    int w    = (blockIdx.x * blockDim.x + threadIdx.x) >> 5;   // dst node
    int lane = threadIdx.x & 31;
    if (w >= N) return;
    const int eg   = lane >> 3;   // edge slot 0..3
    const int chan = lane & 7;
    const float ad = g_ad2[w];
    const int cnt  = g_cnt[w];
    const int base = w * CAP;
    float acc = 0.f, den = 0.f;
    // self-loop on slot 0
    if (eg == 0) {
        float e = __expf(lrelu(g_as2[w] + ad));
        den += e;
        acc += e * g_h2[w * OUT_CH + chan];
    }
    for (int j = eg; j < cnt; j += 4) {
        int s = g_srclist[base + j];
        float e = __expf(lrelu(g_as2[s] + ad));
        den += e;
        acc += e * g_h2[s * OUT_CH + chan];
    }
    // reduce across the 4 edge slots
    acc += __shfl_xor_sync(0xFFFFFFFFu, acc, 8);
    acc += __shfl_xor_sync(0xFFFFFFFFu, acc, 16);
    den += __shfl_xor_sync(0xFFFFFFFFu, den, 8);
    den += __shfl_xor_sync(0xFFFFFFFFu, den, 16);
    if (lane < OUT_CH) out[w * OUT_CH + lane] = acc / den + b2[lane];
    __syncwarp();
    if (lane == 0) g_cnt[w] = 0;   // restore invariant for next replay
}

// ---------------- launcher ---------------------------------------------------
extern "C" void kernel_launch(void* const* d_in, const int* in_sizes, int n_in,
                              void* d_out, int out_size) {
    const float* x      = (const float*)d_in[0];
    const int*   ei     = (const int*)  d_in[1];   // int32 (JAX x64 disabled)
    const float* W1     = (const float*)d_in[2];
    const float* a_src1 = (const float*)d_in[3];
    const float* a_dst1 = (const float*)d_in[4];
    const float* b1     = (const float*)d_in[5];
    const float* W2     = (const float*)d_in[6];
    const float* a_src2 = (const float*)d_in[7];
    const float* a_dst2 = (const float*)d_in[8];
    const float* b2     = (const float*)d_in[9];
    float*       out    = (float*)      d_out;

    const int N = in_sizes[0] / IN_CH;   // 50000
    const int E = in_sizes[1] / 2;       // 800000

    // side stream + events, created once on the (uncaptured) correctness call
    static cudaStream_t s2 = []() {
        cudaStream_t s; cudaStreamCreateWithFlags(&s, cudaStreamNonBlocking); return s;
    }();
    static cudaEvent_t ev0 = []() {
        cudaEvent_t e; cudaEventCreateWithFlags(&e, cudaEventDisableTiming); return e;
    }();
    static cudaEvent_t ev1 = []() {
        cudaEvent_t e; cudaEventCreateWithFlags(&e, cudaEventDisableTiming); return e;
    }();

    // fork: scatter on s2, gemm1 on main stream
    cudaEventRecord(ev0, 0);
    cudaStreamWaitEvent(s2, ev0, 0);

    // --- branch A (s2): padded-bucket scatter (g_cnt zero by invariant) ---
    {
        int nt = (E + 1) / 2;
        k_scatter<<<(nt + 255) / 256, 256, 0, s2>>>(ei, E);   // launch 1
    }
    cudaEventRecord(ev1, s2);

    // --- branch B (main): layer-1 linear ---
    k_gemm1<<<(N + 15) / 16, 128>>>(x, W1, a_src1, a_dst1, N);  // launch 2

    // probe no-op: makes k_agg1 the 4th launch -> ncu window (launch #6 overall)
    k_probe<<<1, 32>>>();                                       // launch 3

    // join
    cudaStreamWaitEvent(0, ev1, 0);

    // fused layer-1 aggregation + ELU + layer-2 linear
    k_agg1<<<(N * 32 + 255) / 256, 256>>>(b1, W2, a_src2, a_dst2, N);  // launch 4
    // layer-2 aggregation (also restores g_cnt = 0)
    k_agg2<<<(N * 32 + 255) / 256, 256>>>(b2, out, N);                 // launch 5
}